// round 7
// baseline (speedup 1.0000x reference)
#include <cuda_runtime.h>

#define TCOLS 4096
#define BROWS 4096
#define NT 256
#define NW 8
#define WELEM 512          // elements per warp; 16 per lane
#define FULL 0xffffffffu
#define NBLK (2 * BROWS)

// Per-(array,row) results: rows of g_res are {pred_sbp, pred_dbp, lab_sbp, lab_dbp}
__device__ float    g_res[4][BROWS];
__device__ unsigned g_done;   // zero-init; reset by last block each launch

__device__ __forceinline__ float warp_sum(float v) {
    #pragma unroll
    for (int o = 16; o; o >>= 1) v += __shfl_xor_sync(FULL, v, o);
    return v;
}

// Block-reduce 2 float sums + 2 int counts over NW=8 warps; broadcast into out[4].
__device__ __forceinline__ void block_reduce4(float s0, float s1, int c0, int c1,
                                              float out[4], float* redf,
                                              int lane, int wid) {
    s0 = warp_sum(s0);
    s1 = warp_sum(s1);
    c0 = __reduce_add_sync(FULL, c0);
    c1 = __reduce_add_sync(FULL, c1);
    if (lane == 0) {
        redf[0 * NW + wid] = s0;
        redf[1 * NW + wid] = s1;
        redf[2 * NW + wid] = (float)c0;
        redf[3 * NW + wid] = (float)c1;
    }
    __syncthreads();
    if (wid < 4) {
        float v = (lane < NW) ? redf[wid * NW + lane] : 0.f;
        v += __shfl_xor_sync(FULL, v, 4);
        v += __shfl_xor_sync(FULL, v, 2);
        v += __shfl_xor_sync(FULL, v, 1);
        if (lane == 0) redf[32 + wid] = v;
    }
    __syncthreads();
    #pragma unroll
    for (int j = 0; j < 4; j++) out[j] = redf[32 + j];
    __syncthreads();
}

__global__ __launch_bounds__(NT, 6)
void pv_array_kernel(const float* __restrict__ preds,
                     const float* __restrict__ labels,
                     float* __restrict__ out) {
    __shared__ float red[40];
    __shared__ bool  amLast;

    const int tid  = threadIdx.x;
    const int lane = tid & 31;
    const int wid  = tid >> 5;
    const int row  = blockIdx.x & (BROWS - 1);
    const int arr  = blockIdx.x >> 12;          // 0 = preds, 1 = labels

    const float* rowp = (arr ? labels : preds) + (size_t)row * TCOLS;
    const int wb = wid * WELEM;
    const float4* g = (const float4*)(rowp + wb);

    // Clamped duplicate neighbors at row edges -> d == 0 -> never strict peak/valley.
    float wl = 0.f, wr = 0.f;
    if (lane == 0)  wl = rowp[wb > 0 ? wb - 1 : 0];
    if (lane == 31) wr = rowp[wb + WELEM < TCOLS ? wb + WELEM : TCOLS - 1];

    // ---- Load this lane's 16 elements (coalesced float4 groups) ----
    float v[16];
    #pragma unroll
    for (int gi = 0; gi < 4; gi++) {
        float4 a = g[gi * 32 + lane];
        v[4 * gi] = a.x; v[4 * gi + 1] = a.y; v[4 * gi + 2] = a.z; v[4 * gi + 3] = a.w;
    }

    // ---- Pass 1: peak/valley detect (shuffle-stitched windows) ----
    float psum = 0.f, vsum = 0.f;
    unsigned pkm = 0, vym = 0;
    float carry = wl;
    #pragma unroll
    for (int gi = 0; gi < 4; gi++) {
        float lead = (gi < 3) ? __shfl_sync(FULL, v[4 * gi + 4], 0) : wr;
        float lv = __shfl_up_sync(FULL, v[4 * gi + 3], 1);
        if (lane == 0) lv = carry;
        float rv = __shfl_down_sync(FULL, v[4 * gi], 1);
        if (lane == 31) rv = lead;

        float e0 = v[4 * gi], e1 = v[4 * gi + 1], e2 = v[4 * gi + 2], e3 = v[4 * gi + 3];
        float d[5];
        d[0] = e0 - lv; d[1] = e1 - e0; d[2] = e2 - e1; d[3] = e3 - e2; d[4] = rv - e3;
        float e[4] = {e0, e1, e2, e3};
        #pragma unroll
        for (int k = 0; k < 4; k++) {
            bool pk = fminf(d[k], -d[k + 1]) > 0.f;   // d[k]>0 && d[k+1]<0
            bool vy = fmaxf(d[k], -d[k + 1]) < 0.f;   // d[k]<0 && d[k+1]>0
            if (pk) { psum += e[k]; pkm |= 1u << (4 * gi + k); }
            if (vy) { vsum += e[k]; vym |= 1u << (4 * gi + k); }
        }
        carry = __shfl_sync(FULL, v[4 * gi + 3], 31);
    }

    float o1[4];
    block_reduce4(psum, vsum, __popc(pkm), __popc(vym), o1, red, lane, wid);
    const float pm = o1[0] / o1[2];
    const float vm = o1[1] / o1[3];

    // ---- Pass 2: thresholded masked means, straight from registers ----
    float s0 = 0.f, s1 = 0.f;
    unsigned m0 = 0, m1 = 0;
    #pragma unroll
    for (int k = 0; k < 16; k++) {
        const unsigned bit = 1u << k;
        if ((pkm & bit) && v[k] >= pm) { s0 += v[k]; m0 |= bit; }
        if ((vym & bit) && v[k] <= vm) { s1 += v[k]; m1 |= bit; }
    }

    float o2[4];
    block_reduce4(s0, s1, __popc(m0), __popc(m1), o2, red, lane, wid);

    if (tid == 0) {
        g_res[(arr << 1) + 0][row] = o2[0] / o2[2];   // sbp
        g_res[(arr << 1) + 1][row] = o2[1] / o2[3];   // dbp
        __threadfence();
        unsigned c = atomicAdd(&g_done, 1u);
        amLast = (c == (unsigned)(NBLK - 1));
    }
    __syncthreads();

    // ---- Last block: combine per-row results into the scalar loss ----
    if (amLast) {
        float acc = 0.f;
        #pragma unroll
        for (int q = 0; q < BROWS / NT; q++) {
            int r = tid + q * NT;
            float d0 = g_res[0][r] - g_res[2][r];
            float d1 = g_res[1][r] - g_res[3][r];
            acc += d0 * d0 + d1 * d1;
        }
        acc = warp_sum(acc);
        if (lane == 0) red[wid] = acc;
        __syncthreads();
        if (tid == 0) {
            float t = 0.f;
            #pragma unroll
            for (int w = 0; w < NW; w++) t += red[w];
            out[0] = t / (float)(BROWS * 2);
            g_done = 0;
        }
    }
}

extern "C" void kernel_launch(void* const* d_in, const int* in_sizes, int n_in,
                              void* d_out, int out_size) {
    const float* preds  = (const float*)d_in[0];
    const float* labels = (const float*)d_in[1];
    pv_array_kernel<<<NBLK, NT>>>(preds, labels, (float*)d_out);
}